// round 16
// baseline (speedup 1.0000x reference)
#include <cuda_runtime.h>
#include <cuda_bf16.h>

#define LQ   4096
#define NH   8
#define NB   2
#define DD   64
#define BH   (NB*NH)
#define UPAD 48
#define NC   128                // candidate buffer per bh (ncand <= 128)
#define CH   32
#define NCH  (LQ/CH)            // 128
#define KC   64                 // key chunk per block in fused kernel
#define NEG_INF -3.0e38f

// ---------------- scratch (static device globals; no allocation) ----------------
__device__ __align__(16) __nv_bfloat16 g_Kbf[NB*LQ*NH*DD];   // 8.4 MB bf16 copy of K
__device__ float g_M[BH*LQ];                   // approx M (stage 1)
__device__ int   g_cand[BH*NC];                // candidate query indices
__device__ float g_Mref_mx[2*BH*NC];           // per-half partial max of Q.K_s
__device__ float g_Mref_sm[2*BH*NC];           // per-half partial sum of Q.K_s
__device__ int   g_Mtop[BH*UPAD];
__device__ int   g_sel[BH*LQ];                 // -1 or u index
__device__ float g_update[BH*UPAD*DD];         // unnormalized: sum_k exp(s) * V
__device__ float g_rowsum[BH*UPAD];            // sum_k exp(s)
__device__ float g_csum[BH*NCH*DD];
__device__ float g_coff[BH*NCH*DD];

__device__ __forceinline__ int xoff(int b, int l, int h, int d) {
    return ((b*LQ + l)*NH + h)*DD + d;   // (B,L,H,D) layout of all I/O tensors
}

// ---- f32x2 packed-FMA helpers (ptxas will not auto-fuse; must be PTX) ----
__device__ __forceinline__ void ffma2(unsigned long long& d, unsigned long long a, unsigned long long b) {
    asm("fma.rn.f32x2 %0, %1, %2, %0;" : "+l"(d) : "l"(a), "l"(b));
}
__device__ __forceinline__ unsigned long long bcast2(float v) {
    unsigned r = __float_as_uint(v);
    unsigned long long d;
    asm("mov.b64 %0, {%1, %1};" : "=l"(d) : "r"(r));
    return d;
}
__device__ __forceinline__ float lo2(unsigned long long x){ return __uint_as_float((unsigned)(x & 0xffffffffu)); }
__device__ __forceinline__ float hi2(unsigned long long x){ return __uint_as_float((unsigned)(x >> 32)); }

// ---- bf16x2 helpers for the approximate sampled-score pass ----
__device__ __forceinline__ unsigned packbf2(float lohalf, float hihalf) {
    unsigned r;
    asm("cvt.rn.bf16x2.f32 %0, %1, %2;" : "=r"(r) : "f"(hihalf), "f"(lohalf));
    return r;
}
__device__ __forceinline__ void hfma2(unsigned& acc, unsigned a, unsigned b) {
    asm("fma.rn.bf16x2 %0, %1, %2, %0;" : "+r"(acc) : "r"(a), "r"(b));
}
__device__ __forceinline__ float widen2(unsigned acc) {
    float2 f = __bfloat1622float2(*(__nv_bfloat162*)&acc);
    return f.x + f.y;
}
// bf16x2 dot of 16 elems (lane's slice of one head), packed q in qp[8], row in r0,r1
__device__ __forceinline__ float dot16h(const unsigned* qp, uint4 r0, uint4 r1) {
    unsigned acc = 0u;
    hfma2(acc, qp[0], r0.x);
    hfma2(acc, qp[1], r0.y);
    hfma2(acc, qp[2], r0.z);
    hfma2(acc, qp[3], r0.w);
    hfma2(acc, qp[4], r1.x);
    hfma2(acc, qp[5], r1.y);
    hfma2(acc, qp[6], r1.z);
    hfma2(acc, qp[7], r1.w);
    return widen2(acc);
}

// ---------------- Kernel 0: K -> bf16 copy (same layout) ----------------
__global__ __launch_bounds__(256) void k_cvtK(const float* __restrict__ K)
{
    int i = blockIdx.x * 256 + threadIdx.x;              // one float4 per thread
    const float4 v = ((const float4*)K)[i];
    __nv_bfloat162 p0 = __floats2bfloat162_rn(v.x, v.y);
    __nv_bfloat162 p1 = __floats2bfloat162_rn(v.z, v.w);
    uint2 out;
    out.x = *(unsigned*)&p0;
    out.y = *(unsigned*)&p1;
    ((uint2*)g_Kbf)[i] = out;
}

// ---------------- Kernel A: approx M; one warp = (b,l) x ALL 8 heads; idx prefetch ----------------
// (256,6): regs 44->42 (nearly free), occ 49 -> ~75% on a latency-bound gather.
__global__ __launch_bounds__(256, 6) void k_sampleM_bf(
    const float* __restrict__ Q, const int* __restrict__ idxs, int U)
{
    int wid  = threadIdx.x >> 5;
    int lane = threadIdx.x & 31;
    int w    = blockIdx.x * 8 + wid;     // warp id = b*LQ + l
    int b    = w >> 12;
    int l    = w & (LQ - 1);
    int head = lane >> 2;                // 8 heads, 4 lanes each
    int sub  = lane & 3;                 // 16-elem slice within the head

    const float4* qsl = (const float4*)(Q + xoff(b, l, head, sub*16));
    unsigned qp[8];
    #pragma unroll
    for (int j = 0; j < 4; j++) {
        float4 q4 = qsl[j];
        qp[2*j]   = packbf2(q4.x, q4.y);
        qp[2*j+1] = packbf2(q4.z, q4.w);
    }
    const int* idxrow = idxs + l * U;
    const uint4* Kb = (const uint4*)(g_Kbf + (size_t)(b*LQ)*(NH*DD));  // + ki*64 uint4s

    float mxA = NEG_INF, smA = 0.0f;
    float mxB = NEG_INF, smB = 0.0f;
    float mxC = NEG_INF, smC = 0.0f;

    int kiA = __ldg(&idxrow[0]);
    int kiB = __ldg(&idxrow[1]);
    int kiC = __ldg(&idxrow[2]);
    for (int s = 0; s + 3 <= U; s += 3) {        // U=45 = 15*3, no remainder
        const uint4* pA = Kb + kiA*64;           // 1024B = 64 uint4
        const uint4* pB = Kb + kiB*64;
        const uint4* pC = Kb + kiC*64;
        uint4 a0 = pA[2*lane], a1 = pA[2*lane+1];
        uint4 b0 = pB[2*lane], b1 = pB[2*lane+1];
        uint4 c0 = pC[2*lane], c1 = pC[2*lane+1];
        if (s + 6 <= U) {                        // prefetch next iteration's indices
            kiA = __ldg(&idxrow[s + 3]);
            kiB = __ldg(&idxrow[s + 4]);
            kiC = __ldg(&idxrow[s + 5]);
        }
        float dA = dot16h(qp, a0, a1);
        float dB = dot16h(qp, b0, b1);
        float dC = dot16h(qp, c0, c1);
        #pragma unroll
        for (int o = 1; o <= 2; o <<= 1) {
            dA += __shfl_xor_sync(0xffffffffu, dA, o);
            dB += __shfl_xor_sync(0xffffffffu, dB, o);
            dC += __shfl_xor_sync(0xffffffffu, dC, o);
        }
        mxA = fmaxf(mxA, dA); smA += dA;
        mxB = fmaxf(mxB, dB); smB += dB;
        mxC = fmaxf(mxC, dC); smC += dC;
    }
    float mx = fmaxf(fmaxf(mxA, mxB), mxC);
    float sm = smA + smB + smC;
    if (sub == 0)
        g_M[(b*NH + head)*LQ + l] = mx - sm * (1.0f / (float)LQ);
}

// ---------------- Kernel B: candidate radix-select, 2-pass 16-bit, warp-shfl scan ----------------
__global__ __launch_bounds__(256) void k_cand(int ncand)
{
    int bh  = blockIdx.x;
    int tid = threadIdx.x;
    int lane = tid & 31, wrp = tid >> 5;
    __shared__ unsigned skeys[LQ];      // 16 KB (32-bit monotonic keys; use top 16 bits)
    __shared__ int hist[256];
    __shared__ int wsum[8];
    __shared__ int selcnt, s_rank;
    __shared__ unsigned s_prefix;

    for (int i = tid; i < LQ; i += 256) {
        unsigned ub = __float_as_uint(g_M[bh*LQ + i]);
        skeys[i] = (ub & 0x80000000u) ? ~ub : (ub | 0x80000000u);  // monotonic map
        g_sel[bh*LQ + i] = -1;
    }
    for (int i = tid; i < UPAD*DD; i += 256) g_update[bh*UPAD*DD + i] = 0.0f;
    if (tid < UPAD) g_rowsum[bh*UPAD + tid] = 0.0f;
    if (tid == 0) { selcnt = 0; s_prefix = 0; s_rank = ncand; }
    __syncthreads();

    unsigned mask = 0;
    #pragma unroll
    for (int shift = 8; shift >= 0; shift -= 8) {       // 2 passes over 16-bit key
        hist[tid] = 0;
        __syncthreads();
        unsigned prefix = s_prefix;
        #pragma unroll 4
        for (int i = tid; i < LQ; i += 256) {
            unsigned k16 = skeys[i] >> 16;
            if ((k16 & mask) == prefix) atomicAdd(&hist[(k16 >> shift) & 255], 1);
        }
        __syncthreads();
        int h = hist[tid];
        int v = h;
        #pragma unroll
        for (int off = 1; off < 32; off <<= 1) {
            int t = __shfl_down_sync(0xffffffffu, v, off);
            if (lane + off < 32) v += t;
        }
        if (lane == 0) wsum[wrp] = v;
        int r = s_rank;
        __syncthreads();
        int offs = 0;
        #pragma unroll
        for (int ww = 0; ww < 8; ww++) if (ww > wrp) offs += wsum[ww];
        int sd  = v + offs;
        int sd1 = sd - h;
        __syncthreads();
        if (sd >= r && sd1 < r) {
            s_rank   = r - sd1;
            s_prefix = s_prefix | ((unsigned)tid << shift);
        }
        __syncthreads();
        mask |= (0xFFu << shift);
    }

    unsigned T = s_prefix;
    #pragma unroll 4
    for (int i = tid; i < LQ; i += 256) {
        if ((skeys[i] >> 16) > T) {
            int u = atomicAdd(&selcnt, 1);
            g_cand[bh*NC + u] = i;
        }
    }
    __syncthreads();
    for (int i = tid; i < LQ; i += 256) {   // fill from == group (superset semantics)
        if ((skeys[i] >> 16) == T) {
            int u = atomicAdd(&selcnt, 1);
            if (u < ncand) g_cand[bh*NC + u] = i;
        }
    }
    __syncthreads();
    if (tid == 0 && selcnt < ncand) {
        for (int u = selcnt; u < ncand; u++) g_cand[bh*NC + u] = 0;
    }
}

// ---------------- Kernel C: exact fp32 partials; 2 warps per candidate (split U) ----------------
// Warp handles sample range [s0,s1): half 0 -> [0,U/2), half 1 -> [U/2,U). Grid doubles to
// 384 blocks and the per-warp DRAM chain halves (the measured binding constraints).
__global__ __launch_bounds__(256) void k_refine(
    const float* __restrict__ Q, const float* __restrict__ K,
    const int* __restrict__ idxs, int U, int ncand)
{
    int wid  = threadIdx.x >> 5;
    int lane = threadIdx.x & 31;
    int w    = blockIdx.x * 8 + wid;
    int total = BH * ncand;
    if (w >= 2*total) return;
    int half = (w >= total) ? 1 : 0;
    int base = w - half*total;
    int bh   = base / ncand;
    int c    = base - bh * ncand;
    int l = g_cand[bh*NC + c];
    int b = bh >> 3, h = bh & 7;
    int sp = lane >> 4;
    int lq = lane & 15;

    const float4* qrow = (const float4*)(Q + xoff(b, l, h, 0));
    float4 q4 = qrow[lq];
    const int* idxrow = idxs + l * U;

    int s0 = half ? (U/2) : 0;
    int s1 = half ? U : (U/2);

    float mx0 = NEG_INF, sm0 = 0.0f;
    float mx1 = NEG_INF, sm1 = 0.0f;
    float mx2 = NEG_INF, sm2 = 0.0f;
    float mx3 = NEG_INF, sm3 = 0.0f;

    int s = s0;
    for (; s + 8 <= s1; s += 8) {
        int ki0 = __ldg(&idxrow[s + sp]);
        int ki1 = __ldg(&idxrow[s + 2 + sp]);
        int ki2 = __ldg(&idxrow[s + 4 + sp]);
        int ki3 = __ldg(&idxrow[s + 6 + sp]);
        float4 k0 = *(const float4*)(K + xoff(b, ki0, h, 4*lq));
        float4 k1 = *(const float4*)(K + xoff(b, ki1, h, 4*lq));
        float4 k2 = *(const float4*)(K + xoff(b, ki2, h, 4*lq));
        float4 k3 = *(const float4*)(K + xoff(b, ki3, h, 4*lq));
        float d0 = q4.x*k0.x + q4.y*k0.y + q4.z*k0.z + q4.w*k0.w;
        float d1 = q4.x*k1.x + q4.y*k1.y + q4.z*k1.z + q4.w*k1.w;
        float d2 = q4.x*k2.x + q4.y*k2.y + q4.z*k2.z + q4.w*k2.w;
        float d3 = q4.x*k3.x + q4.y*k3.y + q4.z*k3.z + q4.w*k3.w;
        #pragma unroll
        for (int o = 8; o >= 1; o >>= 1) {
            d0 += __shfl_xor_sync(0xffffffffu, d0, o);
            d1 += __shfl_xor_sync(0xffffffffu, d1, o);
            d2 += __shfl_xor_sync(0xffffffffu, d2, o);
            d3 += __shfl_xor_sync(0xffffffffu, d3, o);
        }
        mx0 = fmaxf(mx0, d0); sm0 += d0;
        mx1 = fmaxf(mx1, d1); sm1 += d1;
        mx2 = fmaxf(mx2, d2); sm2 += d2;
        mx3 = fmaxf(mx3, d3); sm3 += d3;
    }
    for (; s < s1; s += 2) {
        int sEff  = s + sp;
        int valid = (sEff < s1);
        int kidx  = valid ? __ldg(&idxrow[sEff]) : __ldg(&idxrow[s0]);
        float4 k4 = *(const float4*)(K + xoff(b, kidx, h, 4*lq));
        float d = q4.x*k4.x + q4.y*k4.y + q4.z*k4.z + q4.w*k4.w;
        #pragma unroll
        for (int o = 8; o >= 1; o >>= 1)
            d += __shfl_xor_sync(0xffffffffu, d, o);
        if (valid) { mx0 = fmaxf(mx0, d); sm0 += d; }
    }
    float mx = fmaxf(fmaxf(mx0, mx1), fmaxf(mx2, mx3));
    float sm = sm0 + sm1 + sm2 + sm3;
    float mxo = __shfl_xor_sync(0xffffffffu, mx, 16);
    float smo = __shfl_xor_sync(0xffffffffu, sm, 16);
    mx = fmaxf(mx, mxo);
    sm += smo;
    if (lane == 0) {
        g_Mref_mx[(half*BH + bh)*NC + c] = mx;
        g_Mref_sm[(half*BH + bh)*NC + c] = sm;
    }
}

// ---------------- Kernel D: combine halves + exact top-U among candidates (1 warp/bh) ----------------
__global__ __launch_bounds__(32) void k_sel45(int U, int ncand)
{
    int bh = blockIdx.x;
    int lane = threadIdx.x;
    float v[4]; int id[4];
    #pragma unroll
    for (int j = 0; j < 4; j++) {
        int c = j*32 + lane;
        if (c < ncand) {
            float mx = fmaxf(g_Mref_mx[bh*NC + c], g_Mref_mx[(BH + bh)*NC + c]);
            float sm = g_Mref_sm[bh*NC + c] + g_Mref_sm[(BH + bh)*NC + c];
            v[j]  = mx - sm * (1.0f / (float)LQ);
            id[j] = g_cand[bh*NC + c];
        } else { v[j] = NEG_INF; id[j] = 0x7FFFFFFF; }
    }
    for (int u = 0; u < U; u++) {
        float lv = NEG_INF; int li = 0x7FFFFFFF, slot = -1;
        #pragma unroll
        for (int j = 0; j < 4; j++) {
            if (v[j] > lv || (v[j] == lv && id[j] < li)) { lv = v[j]; li = id[j]; slot = j; }
        }
        float bv = lv; int bi = li;
        #pragma unroll
        for (int o = 16; o >= 1; o >>= 1) {
            float ov = __shfl_xor_sync(0xffffffffu, bv, o);
            int   oi = __shfl_xor_sync(0xffffffffu, bi, o);
            if (ov > bv || (ov == bv && oi < bi)) { bv = ov; bi = oi; }
        }
        if (lv == bv && li == bi) {         // unique owner (indices distinct)
            v[slot] = NEG_INF;
            g_sel[bh*LQ + bi] = u;
        }
        if (lane == 0) g_Mtop[bh*UPAD + u] = bi;
    }
}

// ---------------- Kernel E: fused scores -> exp -> (exp@V); ONE KC=64 chunk per block ----------------
__global__ __launch_bounds__(256) void k_fused(
    const float* __restrict__ Q, const float* __restrict__ K,
    const float* __restrict__ V, int U)
{
    int bh = blockIdx.y;
    int b = bh >> 3, h = bh & 7;
    int k0 = blockIdx.x * KC;
    __shared__ float Qs[UPAD*66];   // [u][d] stride 66
    __shared__ float Ks[KC*66];     // [k][d] stride 66; reused as Ps[u][k]
    __shared__ float Vs[KC*66];     // [k][d] stride 66
    int tid = threadIdx.x;
    int tx = tid & 15, ty = tid >> 4;

    for (int i = tid; i < UPAD*DD; i += 256) {
        int u = i >> 6, d = i & 63;
        float v = 0.0f;
        if (u < U) { int l = g_Mtop[bh*UPAD + u]; v = Q[xoff(b, l, h, d)]; }
        Qs[u*66 + d] = v;
    }
    for (int i = tid; i < KC*DD; i += 256) {
        int k = i >> 6, d = i & 63;
        Ks[k*66 + d] = K[xoff(b, k0 + k, h, d)];
        Vs[k*66 + d] = V[xoff(b, k0 + k, h, d)];
    }
    __syncthreads();

    unsigned long long acc[3][4];
    #pragma unroll
    for (int j = 0; j < 3; j++)
        #pragma unroll
        for (int i = 0; i < 4; i++) acc[j][i] = 0ull;

    #pragma unroll 8
    for (int di = 0; di < 32; di++) {
        unsigned long long q2[3], k2[4];
        #pragma unroll
        for (int j = 0; j < 3; j++)
            q2[j] = *(const unsigned long long*)&Qs[(ty + 16*j)*66 + 2*di];
        #pragma unroll
        for (int i = 0; i < 4; i++)
            k2[i] = *(const unsigned long long*)&Ks[(tx + 16*i)*66 + 2*di];
        #pragma unroll
        for (int j = 0; j < 3; j++)
            #pragma unroll
            for (int i = 0; i < 4; i++) ffma2(acc[j][i], q2[j], k2[i]);
    }

    float ev[3][4];
    float rsum[3];
    #pragma unroll
    for (int j = 0; j < 3; j++) {
        rsum[j] = 0.0f;
        #pragma unroll
        for (int i = 0; i < 4; i++) {
            float sc = (lo2(acc[j][i]) + hi2(acc[j][i])) * 0.125f;  // 1/sqrt(64)
            float e = __expf(sc);
            ev[j][i] = e;
            rsum[j] += e;
        }
    }
    #pragma unroll
    for (int j = 0; j < 3; j++) {
        #pragma unroll
        for (int o = 8; o >= 1; o >>= 1)
            rsum[j] += __shfl_xor_sync(0xffffffffu, rsum[j], o);
    }
    if (tx == 0) {
        #pragma unroll
        for (int j = 0; j < 3; j++)
            atomicAdd(&g_rowsum[bh*UPAD + ty + 16*j], rsum[j]);
    }

    __syncthreads();
    float* Ps = Ks;             // reuse buffer as Ps[u][k] stride 66
    #pragma unroll
    for (int j = 0; j < 3; j++)
        #pragma unroll
        for (int i = 0; i < 4; i++)
            Ps[(ty + 16*j)*66 + tx + 16*i] = ev[j][i];
    __syncthreads();

    unsigned long long o2[3][2];
    #pragma unroll
    for (int j = 0; j < 3; j++) { o2[j][0] = 0ull; o2[j][1] = 0ull; }

    #pragma unroll 8
    for (int k = 0; k < KC; k++) {
        unsigned long long p2[3], v2[2];
        #pragma unroll
        for (int j = 0; j < 3; j++) p2[j] = bcast2(Ps[(ty + 16*j)*66 + k]);
        #pragma unroll
        for (int i = 0; i < 2; i++)
            v2[i] = *(const unsigned long long*)&Vs[k*66 + 2*(tx + 16*i)];
        #pragma unroll
        for (int j = 0; j < 3; j++)
            #pragma unroll
            for (int i = 0; i < 2; i++) ffma2(o2[j][i], p2[j], v2[i]);
    }

    #pragma unroll
    for (int j = 0; j < 3; j++) {
        int u = ty + 16*j;
        #pragma unroll
        for (int i = 0; i < 2; i++) {
            int d = 2*(tx + 16*i);
            atomicAdd(&g_update[(bh*UPAD + u)*DD + d],     lo2(o2[j][i]));
            atomicAdd(&g_update[(bh*UPAD + u)*DD + d + 1], hi2(o2[j][i]));
        }
    }
}

// ---------------- Kernel F1: per-chunk V sums (256 thr, 4-way k-split, depth 8) ----------------
__global__ __launch_bounds__(256) void k_csum1(const float* __restrict__ V)
{
    int ch = blockIdx.x, bh = blockIdx.y;
    int b = bh >> 3, h = bh & 7;
    int d = threadIdx.x & 63, seg = threadIdx.x >> 6;
    __shared__ float part[4][DD];
    float acc = 0.0f;
    int base = xoff(b, ch*CH + seg*8, h, d);
    #pragma unroll
    for (int i = 0; i < 8; i++) acc += V[base + i*(NH*DD)];
    part[seg][d] = acc;
    __syncthreads();
    if (threadIdx.x < 64)
        g_csum[(bh*NCH + ch)*DD + d] = part[0][d] + part[1][d] + part[2][d] + part[3][d];
}

// ---------------- Kernel F2: exclusive scan of chunk sums ----------------
__global__ __launch_bounds__(1024) void k_csum2()
{
    int t = threadIdx.x;           // 1024 = BH*DD
    int bh = t >> 6, d = t & 63;
    float run = 0.0f;
    #pragma unroll 8
    for (int ch = 0; ch < NCH; ch++) {
        int ix = (bh*NCH + ch)*DD + d;
        float v = g_csum[ix];
        g_coff[ix] = run;
        run += v;
    }
}

// ---------------- Kernel F3: final cumsum + scatter; 256 thr, 4 segs x 8 rows ----------------
__global__ __launch_bounds__(256) void k_final(const float* __restrict__ V, float* __restrict__ out)
{
    int ch = blockIdx.x, bh = blockIdx.y;
    int b = bh >> 3, h = bh & 7;
    int d = threadIdx.x & 63, seg = threadIdx.x >> 6;
    __shared__ float segsum[4][DD];
    int l0 = ch*CH + seg*8;

    float v[8];
    float tot = 0.0f;
    #pragma unroll
    for (int i = 0; i < 8; i++) { v[i] = V[xoff(b, l0 + i, h, d)]; tot += v[i]; }
    segsum[seg][d] = tot;
    __syncthreads();

    float acc = g_coff[(bh*NCH + ch)*DD + d];
    #pragma unroll
    for (int ss = 0; ss < 3; ss++) if (ss < seg) acc += segsum[ss][d];

    #pragma unroll
    for (int i = 0; i < 8; i++) {
        int l = l0 + i;
        acc += v[i];
        int s = __ldg(&g_sel[bh*LQ + l]);
        int o = xoff(b, l, h, d);
        if (s >= 0) {
            float inv = 1.0f / __ldg(&g_rowsum[bh*UPAD + s]);
            out[o] = g_update[(bh*UPAD + s)*DD + d] * inv;
        } else {
            out[o] = acc;
        }
    }
}

// ---------------- launch ----------------
// Order: slot 4 = the split-U k_refine (verify the grid-parallelism cut).
extern "C" void kernel_launch(void* const* d_in, const int* in_sizes, int n_in,
                              void* d_out, int out_size)
{
    const float* Q   = (const float*)d_in[0];
    const float* K   = (const float*)d_in[1];
    const float* V   = (const float*)d_in[2];
    const int*   idx = (const int*)  d_in[3];
    float* out = (float*)d_out;
    int U = in_sizes[3] / LQ;     // 45
    int ncand = (2*U + 6 <= NC) ? 2*U + 6 : NC;   // 96 for U=45
    const int NF4 = NB*LQ*NH*DD/4;                 // total float4 elems in K

    k_cvtK     <<<NF4/256, 256>>>(K);                        // 1
    k_sampleM_bf<<<NB*LQ/8, 256>>>(Q, idx, U);               // 2
    k_cand     <<<BH, 256>>>(ncand);                         // 3
    k_refine   <<<(2*BH*ncand + 7)/8, 256>>>(Q, K, idx, U, ncand); // 4  <- profiled (384 blocks)
    k_sel45    <<<BH, 32>>>(U, ncand);                       // 5
    k_fused    <<<dim3(LQ/KC, BH), 256>>>(Q, K, V, U);       // 6
    k_csum1    <<<dim3(NCH, BH), 256>>>(V);                  // 7
    k_csum2    <<<1, 1024>>>();                              // 8
    k_final    <<<dim3(NCH, BH), 256>>>(V, out);             // 9
}

// round 17
// speedup vs baseline: 1.0291x; 1.0291x over previous
#include <cuda_runtime.h>
#include <cuda_bf16.h>

#define LQ   4096
#define NH   8
#define NB   2
#define DD   64
#define BH   (NB*NH)
#define UPAD 48
#define NC   128                // candidate buffer per bh (ncand <= 128)
#define CH   32
#define NCH  (LQ/CH)            // 128
#define KC   64                 // key chunk per block in fused kernel
#define NEG_INF -3.0e38f

// ---------------- scratch (static device globals; no allocation) ----------------
__device__ __align__(16) __nv_bfloat16 g_Kbf[NB*LQ*NH*DD];   // 8.4 MB bf16 copy of K
__device__ float g_M[BH*LQ];                   // approx M (stage 1)
__device__ int   g_cand[BH*NC];                // candidate query indices
__device__ float g_Mref_mx[2*BH*NC];           // per-half partial max of Q.K_s
__device__ float g_Mref_sm[2*BH*NC];           // per-half partial sum of Q.K_s
__device__ int   g_Mtop[BH*UPAD];
__device__ int   g_sel[BH*LQ];                 // -1 or u index
__device__ float g_update[BH*UPAD*DD];         // unnormalized: sum_k exp(s) * V
__device__ float g_rowsum[BH*UPAD];            // sum_k exp(s)
__device__ float g_csum[BH*NCH*DD];
__device__ float g_coff[BH*NCH*DD];

__device__ __forceinline__ int xoff(int b, int l, int h, int d) {
    return ((b*LQ + l)*NH + h)*DD + d;   // (B,L,H,D) layout of all I/O tensors
}

// ---- f32x2 packed-FMA helpers (ptxas will not auto-fuse; must be PTX) ----
__device__ __forceinline__ void ffma2(unsigned long long& d, unsigned long long a, unsigned long long b) {
    asm("fma.rn.f32x2 %0, %1, %2, %0;" : "+l"(d) : "l"(a), "l"(b));
}
__device__ __forceinline__ unsigned long long bcast2(float v) {
    unsigned r = __float_as_uint(v);
    unsigned long long d;
    asm("mov.b64 %0, {%1, %1};" : "=l"(d) : "r"(r));
    return d;
}
__device__ __forceinline__ float lo2(unsigned long long x){ return __uint_as_float((unsigned)(x & 0xffffffffu)); }
__device__ __forceinline__ float hi2(unsigned long long x){ return __uint_as_float((unsigned)(x >> 32)); }

// ---- bf16x2 helpers for the approximate sampled-score pass ----
__device__ __forceinline__ unsigned packbf2(float lohalf, float hihalf) {
    unsigned r;
    asm("cvt.rn.bf16x2.f32 %0, %1, %2;" : "=r"(r) : "f"(hihalf), "f"(lohalf));
    return r;
}
__device__ __forceinline__ void hfma2(unsigned& acc, unsigned a, unsigned b) {
    asm("fma.rn.bf16x2 %0, %1, %2, %0;" : "+r"(acc) : "r"(a), "r"(b));
}
__device__ __forceinline__ float widen2(unsigned acc) {
    float2 f = __bfloat1622float2(*(__nv_bfloat162*)&acc);
    return f.x + f.y;
}
// bf16x2 dot of 16 elems (lane's slice of one head), packed q in qp[8], row in r0,r1
__device__ __forceinline__ float dot16h(const unsigned* qp, uint4 r0, uint4 r1) {
    unsigned acc = 0u;
    hfma2(acc, qp[0], r0.x);
    hfma2(acc, qp[1], r0.y);
    hfma2(acc, qp[2], r0.z);
    hfma2(acc, qp[3], r0.w);
    hfma2(acc, qp[4], r1.x);
    hfma2(acc, qp[5], r1.y);
    hfma2(acc, qp[6], r1.z);
    hfma2(acc, qp[7], r1.w);
    return widen2(acc);
}

// ---------------- Kernel 0: K -> bf16 copy (same layout) ----------------
__global__ __launch_bounds__(256) void k_cvtK(const float* __restrict__ K)
{
    int i = blockIdx.x * 256 + threadIdx.x;              // one float4 per thread
    const float4 v = ((const float4*)K)[i];
    __nv_bfloat162 p0 = __floats2bfloat162_rn(v.x, v.y);
    __nv_bfloat162 p1 = __floats2bfloat162_rn(v.z, v.w);
    uint2 out;
    out.x = *(unsigned*)&p0;
    out.y = *(unsigned*)&p1;
    ((uint2*)g_Kbf)[i] = out;
}

// ---------------- Kernel A: approx M; one warp = (b,l) x ALL 8 heads; idx prefetch ----------------
// UNCAPPED (measured best 34.7us; the (256,6) cap regressed twice — ptxas respill)
__global__ __launch_bounds__(256) void k_sampleM_bf(
    const float* __restrict__ Q, const int* __restrict__ idxs, int U)
{
    int wid  = threadIdx.x >> 5;
    int lane = threadIdx.x & 31;
    int w    = blockIdx.x * 8 + wid;     // warp id = b*LQ + l
    int b    = w >> 12;
    int l    = w & (LQ - 1);
    int head = lane >> 2;                // 8 heads, 4 lanes each
    int sub  = lane & 3;                 // 16-elem slice within the head

    const float4* qsl = (const float4*)(Q + xoff(b, l, head, sub*16));
    unsigned qp[8];
    #pragma unroll
    for (int j = 0; j < 4; j++) {
        float4 q4 = qsl[j];
        qp[2*j]   = packbf2(q4.x, q4.y);
        qp[2*j+1] = packbf2(q4.z, q4.w);
    }
    const int* idxrow = idxs + l * U;
    const uint4* Kb = (const uint4*)(g_Kbf + (size_t)(b*LQ)*(NH*DD));  // + ki*64 uint4s

    float mxA = NEG_INF, smA = 0.0f;
    float mxB = NEG_INF, smB = 0.0f;
    float mxC = NEG_INF, smC = 0.0f;

    int kiA = __ldg(&idxrow[0]);
    int kiB = __ldg(&idxrow[1]);
    int kiC = __ldg(&idxrow[2]);
    for (int s = 0; s + 3 <= U; s += 3) {        // U=45 = 15*3, no remainder
        const uint4* pA = Kb + kiA*64;           // 1024B = 64 uint4
        const uint4* pB = Kb + kiB*64;
        const uint4* pC = Kb + kiC*64;
        uint4 a0 = pA[2*lane], a1 = pA[2*lane+1];
        uint4 b0 = pB[2*lane], b1 = pB[2*lane+1];
        uint4 c0 = pC[2*lane], c1 = pC[2*lane+1];
        if (s + 6 <= U) {                        // prefetch next iteration's indices
            kiA = __ldg(&idxrow[s + 3]);
            kiB = __ldg(&idxrow[s + 4]);
            kiC = __ldg(&idxrow[s + 5]);
        }
        float dA = dot16h(qp, a0, a1);
        float dB = dot16h(qp, b0, b1);
        float dC = dot16h(qp, c0, c1);
        #pragma unroll
        for (int o = 1; o <= 2; o <<= 1) {
            dA += __shfl_xor_sync(0xffffffffu, dA, o);
            dB += __shfl_xor_sync(0xffffffffu, dB, o);
            dC += __shfl_xor_sync(0xffffffffu, dC, o);
        }
        mxA = fmaxf(mxA, dA); smA += dA;
        mxB = fmaxf(mxB, dB); smB += dB;
        mxC = fmaxf(mxC, dC); smC += dC;
    }
    float mx = fmaxf(fmaxf(mxA, mxB), mxC);
    float sm = smA + smB + smC;
    if (sub == 0)
        g_M[(b*NH + head)*LQ + l] = mx - sm * (1.0f / (float)LQ);
}

// ---------------- Kernel B: candidate radix-select, 2-pass 16-bit, warp-shfl scan ----------------
__global__ __launch_bounds__(256) void k_cand(int ncand)
{
    int bh  = blockIdx.x;
    int tid = threadIdx.x;
    int lane = tid & 31, wrp = tid >> 5;
    __shared__ unsigned skeys[LQ];      // 16 KB (32-bit monotonic keys; use top 16 bits)
    __shared__ int hist[256];
    __shared__ int wsum[8];
    __shared__ int selcnt, s_rank;
    __shared__ unsigned s_prefix;

    for (int i = tid; i < LQ; i += 256) {
        unsigned ub = __float_as_uint(g_M[bh*LQ + i]);
        skeys[i] = (ub & 0x80000000u) ? ~ub : (ub | 0x80000000u);  // monotonic map
        g_sel[bh*LQ + i] = -1;
    }
    for (int i = tid; i < UPAD*DD; i += 256) g_update[bh*UPAD*DD + i] = 0.0f;
    if (tid < UPAD) g_rowsum[bh*UPAD + tid] = 0.0f;
    if (tid == 0) { selcnt = 0; s_prefix = 0; s_rank = ncand; }
    __syncthreads();

    unsigned mask = 0;
    #pragma unroll
    for (int shift = 8; shift >= 0; shift -= 8) {       // 2 passes over 16-bit key
        hist[tid] = 0;
        __syncthreads();
        unsigned prefix = s_prefix;
        #pragma unroll 4
        for (int i = tid; i < LQ; i += 256) {
            unsigned k16 = skeys[i] >> 16;
            if ((k16 & mask) == prefix) atomicAdd(&hist[(k16 >> shift) & 255], 1);
        }
        __syncthreads();
        int h = hist[tid];
        int v = h;
        #pragma unroll
        for (int off = 1; off < 32; off <<= 1) {
            int t = __shfl_down_sync(0xffffffffu, v, off);
            if (lane + off < 32) v += t;
        }
        if (lane == 0) wsum[wrp] = v;
        int r = s_rank;
        __syncthreads();
        int offs = 0;
        #pragma unroll
        for (int ww = 0; ww < 8; ww++) if (ww > wrp) offs += wsum[ww];
        int sd  = v + offs;
        int sd1 = sd - h;
        __syncthreads();
        if (sd >= r && sd1 < r) {
            s_rank   = r - sd1;
            s_prefix = s_prefix | ((unsigned)tid << shift);
        }
        __syncthreads();
        mask |= (0xFFu << shift);
    }

    unsigned T = s_prefix;
    #pragma unroll 4
    for (int i = tid; i < LQ; i += 256) {
        if ((skeys[i] >> 16) > T) {
            int u = atomicAdd(&selcnt, 1);
            g_cand[bh*NC + u] = i;
        }
    }
    __syncthreads();
    for (int i = tid; i < LQ; i += 256) {   // fill from == group (superset semantics)
        if ((skeys[i] >> 16) == T) {
            int u = atomicAdd(&selcnt, 1);
            if (u < ncand) g_cand[bh*NC + u] = i;
        }
    }
    __syncthreads();
    if (tid == 0 && selcnt < ncand) {
        for (int u = selcnt; u < ncand; u++) g_cand[bh*NC + u] = 0;
    }
}

// ---------------- Kernel C: exact fp32 partials; 2 warps per candidate (split U) ----------------
__global__ __launch_bounds__(256) void k_refine(
    const float* __restrict__ Q, const float* __restrict__ K,
    const int* __restrict__ idxs, int U, int ncand)
{
    int wid  = threadIdx.x >> 5;
    int lane = threadIdx.x & 31;
    int w    = blockIdx.x * 8 + wid;
    int total = BH * ncand;
    if (w >= 2*total) return;
    int half = (w >= total) ? 1 : 0;
    int base = w - half*total;
    int bh   = base / ncand;
    int c    = base - bh * ncand;
    int l = g_cand[bh*NC + c];
    int b = bh >> 3, h = bh & 7;
    int sp = lane >> 4;
    int lq = lane & 15;

    const float4* qrow = (const float4*)(Q + xoff(b, l, h, 0));
    float4 q4 = qrow[lq];
    const int* idxrow = idxs + l * U;

    int s0 = half ? (U/2) : 0;
    int s1 = half ? U : (U/2);

    float mx0 = NEG_INF, sm0 = 0.0f;
    float mx1 = NEG_INF, sm1 = 0.0f;
    float mx2 = NEG_INF, sm2 = 0.0f;
    float mx3 = NEG_INF, sm3 = 0.0f;

    int s = s0;
    for (; s + 8 <= s1; s += 8) {
        int ki0 = __ldg(&idxrow[s + sp]);
        int ki1 = __ldg(&idxrow[s + 2 + sp]);
        int ki2 = __ldg(&idxrow[s + 4 + sp]);
        int ki3 = __ldg(&idxrow[s + 6 + sp]);
        float4 k0 = *(const float4*)(K + xoff(b, ki0, h, 4*lq));
        float4 k1 = *(const float4*)(K + xoff(b, ki1, h, 4*lq));
        float4 k2 = *(const float4*)(K + xoff(b, ki2, h, 4*lq));
        float4 k3 = *(const float4*)(K + xoff(b, ki3, h, 4*lq));
        float d0 = q4.x*k0.x + q4.y*k0.y + q4.z*k0.z + q4.w*k0.w;
        float d1 = q4.x*k1.x + q4.y*k1.y + q4.z*k1.z + q4.w*k1.w;
        float d2 = q4.x*k2.x + q4.y*k2.y + q4.z*k2.z + q4.w*k2.w;
        float d3 = q4.x*k3.x + q4.y*k3.y + q4.z*k3.z + q4.w*k3.w;
        #pragma unroll
        for (int o = 8; o >= 1; o >>= 1) {
            d0 += __shfl_xor_sync(0xffffffffu, d0, o);
            d1 += __shfl_xor_sync(0xffffffffu, d1, o);
            d2 += __shfl_xor_sync(0xffffffffu, d2, o);
            d3 += __shfl_xor_sync(0xffffffffu, d3, o);
        }
        mx0 = fmaxf(mx0, d0); sm0 += d0;
        mx1 = fmaxf(mx1, d1); sm1 += d1;
        mx2 = fmaxf(mx2, d2); sm2 += d2;
        mx3 = fmaxf(mx3, d3); sm3 += d3;
    }
    for (; s < s1; s += 2) {
        int sEff  = s + sp;
        int valid = (sEff < s1);
        int kidx  = valid ? __ldg(&idxrow[sEff]) : __ldg(&idxrow[s0]);
        float4 k4 = *(const float4*)(K + xoff(b, kidx, h, 4*lq));
        float d = q4.x*k4.x + q4.y*k4.y + q4.z*k4.z + q4.w*k4.w;
        #pragma unroll
        for (int o = 8; o >= 1; o >>= 1)
            d += __shfl_xor_sync(0xffffffffu, d, o);
        if (valid) { mx0 = fmaxf(mx0, d); sm0 += d; }
    }
    float mx = fmaxf(fmaxf(mx0, mx1), fmaxf(mx2, mx3));
    float sm = sm0 + sm1 + sm2 + sm3;
    float mxo = __shfl_xor_sync(0xffffffffu, mx, 16);
    float smo = __shfl_xor_sync(0xffffffffu, sm, 16);
    mx = fmaxf(mx, mxo);
    sm += smo;
    if (lane == 0) {
        g_Mref_mx[(half*BH + bh)*NC + c] = mx;
        g_Mref_sm[(half*BH + bh)*NC + c] = sm;
    }
}

// ---------------- Kernel D: combine halves + exact top-U among candidates (1 warp/bh) ----------------
__global__ __launch_bounds__(32) void k_sel45(int U, int ncand)
{
    int bh = blockIdx.x;
    int lane = threadIdx.x;
    float v[4]; int id[4];
    #pragma unroll
    for (int j = 0; j < 4; j++) {
        int c = j*32 + lane;
        if (c < ncand) {
            float mx = fmaxf(g_Mref_mx[bh*NC + c], g_Mref_mx[(BH + bh)*NC + c]);
            float sm = g_Mref_sm[bh*NC + c] + g_Mref_sm[(BH + bh)*NC + c];
            v[j]  = mx - sm * (1.0f / (float)LQ);
            id[j] = g_cand[bh*NC + c];
        } else { v[j] = NEG_INF; id[j] = 0x7FFFFFFF; }
    }
    for (int u = 0; u < U; u++) {
        float lv = NEG_INF; int li = 0x7FFFFFFF, slot = -1;
        #pragma unroll
        for (int j = 0; j < 4; j++) {
            if (v[j] > lv || (v[j] == lv && id[j] < li)) { lv = v[j]; li = id[j]; slot = j; }
        }
        float bv = lv; int bi = li;
        #pragma unroll
        for (int o = 16; o >= 1; o >>= 1) {
            float ov = __shfl_xor_sync(0xffffffffu, bv, o);
            int   oi = __shfl_xor_sync(0xffffffffu, bi, o);
            if (ov > bv || (ov == bv && oi < bi)) { bv = ov; bi = oi; }
        }
        if (lv == bv && li == bi) {         // unique owner (indices distinct)
            v[slot] = NEG_INF;
            g_sel[bh*LQ + bi] = u;
        }
        if (lane == 0) g_Mtop[bh*UPAD + u] = bi;
    }
}

// ---------------- Kernel E: fused scores -> exp -> (exp@V); GEMM2 with paired-k P loads ----------------
__global__ __launch_bounds__(256) void k_fused(
    const float* __restrict__ Q, const float* __restrict__ K,
    const float* __restrict__ V, int U)
{
    int bh = blockIdx.y;
    int b = bh >> 3, h = bh & 7;
    int k0 = blockIdx.x * KC;
    __shared__ float Qs[UPAD*66];   // [u][d] stride 66
    __shared__ float Ks[KC*66];     // [k][d] stride 66; reused as Ps[u][k]
    __shared__ float Vs[KC*66];     // [k][d] stride 66
    int tid = threadIdx.x;
    int tx = tid & 15, ty = tid >> 4;

    for (int i = tid; i < UPAD*DD; i += 256) {
        int u = i >> 6, d = i & 63;
        float v = 0.0f;
        if (u < U) { int l = g_Mtop[bh*UPAD + u]; v = Q[xoff(b, l, h, d)]; }
        Qs[u*66 + d] = v;
    }
    for (int i = tid; i < KC*DD; i += 256) {
        int k = i >> 6, d = i & 63;
        Ks[k*66 + d] = K[xoff(b, k0 + k, h, d)];
        Vs[k*66 + d] = V[xoff(b, k0 + k, h, d)];
    }
    __syncthreads();

    unsigned long long acc[3][4];
    #pragma unroll
    for (int j = 0; j < 3; j++)
        #pragma unroll
        for (int i = 0; i < 4; i++) acc[j][i] = 0ull;

    #pragma unroll 8
    for (int di = 0; di < 32; di++) {
        unsigned long long q2[3], k2[4];
        #pragma unroll
        for (int j = 0; j < 3; j++)
            q2[j] = *(const unsigned long long*)&Qs[(ty + 16*j)*66 + 2*di];
        #pragma unroll
        for (int i = 0; i < 4; i++)
            k2[i] = *(const unsigned long long*)&Ks[(tx + 16*i)*66 + 2*di];
        #pragma unroll
        for (int j = 0; j < 3; j++)
            #pragma unroll
            for (int i = 0; i < 4; i++) ffma2(acc[j][i], q2[j], k2[i]);
    }

    float ev[3][4];
    float rsum[3];
    #pragma unroll
    for (int j = 0; j < 3; j++) {
        rsum[j] = 0.0f;
        #pragma unroll
        for (int i = 0; i < 4; i++) {
            float sc = (lo2(acc[j][i]) + hi2(acc[j][i])) * 0.125f;  // 1/sqrt(64)
            float e = __expf(sc);
            ev[j][i] = e;
            rsum[j] += e;
        }
    }
    #pragma unroll
    for (int j = 0; j < 3; j++) {
        #pragma unroll
        for (int o = 8; o >= 1; o >>= 1)
            rsum[j] += __shfl_xor_sync(0xffffffffu, rsum[j], o);
    }
    if (tx == 0) {
        #pragma unroll
        for (int j = 0; j < 3; j++)
            atomicAdd(&g_rowsum[bh*UPAD + ty + 16*j], rsum[j]);
    }

    __syncthreads();
    float* Ps = Ks;             // reuse buffer as Ps[u][k] stride 66
    #pragma unroll
    for (int j = 0; j < 3; j++)
        #pragma unroll
        for (int i = 0; i < 4; i++)
            Ps[(ty + 16*j)*66 + tx + 16*i] = ev[j][i];
    __syncthreads();

    unsigned long long o2[3][2];
    #pragma unroll
    for (int j = 0; j < 3; j++) { o2[j][0] = 0ull; o2[j][1] = 0ull; }

    // k processed in PAIRS: one LDS.64 per (u, k-pair) for P (k even, 8B-aligned),
    // broadcasts from register; v2 loads per k as before. ~30% fewer GEMM2 LDS ops.
    #pragma unroll 4
    for (int k = 0; k < KC; k += 2) {
        unsigned long long pp[3];
        #pragma unroll
        for (int j = 0; j < 3; j++)
            pp[j] = *(const unsigned long long*)&Ps[(ty + 16*j)*66 + k];
        unsigned long long v2a[2], v2b[2];
        #pragma unroll
        for (int i = 0; i < 2; i++) {
            v2a[i] = *(const unsigned long long*)&Vs[k*66 + 2*(tx + 16*i)];
            v2b[i] = *(const unsigned long long*)&Vs[(k+1)*66 + 2*(tx + 16*i)];
        }
        #pragma unroll
        for (int j = 0; j < 3; j++) {
            unsigned long long pa = bcast2(lo2(pp[j]));
            unsigned long long pb = bcast2(hi2(pp[j]));
            #pragma unroll
            for (int i = 0; i < 2; i++) {
                ffma2(o2[j][i], pa, v2a[i]);
                ffma2(o2[j][i], pb, v2b[i]);
            }
        }
    }

    #pragma unroll
    for (int j = 0; j < 3; j++) {
        int u = ty + 16*j;
        #pragma unroll
        for (int i = 0; i < 2; i++) {
            int d = 2*(tx + 16*i);
            atomicAdd(&g_update[(bh*UPAD + u)*DD + d],     lo2(o2[j][i]));
            atomicAdd(&g_update[(bh*UPAD + u)*DD + d + 1], hi2(o2[j][i]));
        }
    }
}

// ---------------- Kernel F1: per-chunk V sums (256 thr, 4-way k-split, depth 8) ----------------
__global__ __launch_bounds__(256) void k_csum1(const float* __restrict__ V)
{
    int ch = blockIdx.x, bh = blockIdx.y;
    int b = bh >> 3, h = bh & 7;
    int d = threadIdx.x & 63, seg = threadIdx.x >> 6;
    __shared__ float part[4][DD];
    float acc = 0.0f;
    int base = xoff(b, ch*CH + seg*8, h, d);
    #pragma unroll
    for (int i = 0; i < 8; i++) acc += V[base + i*(NH*DD)];
    part[seg][d] = acc;
    __syncthreads();
    if (threadIdx.x < 64)
        g_csum[(bh*NCH + ch)*DD + d] = part[0][d] + part[1][d] + part[2][d] + part[3][d];
}

// ---------------- Kernel F2: exclusive scan of chunk sums ----------------
__global__ __launch_bounds__(1024) void k_csum2()
{
    int t = threadIdx.x;           // 1024 = BH*DD
    int bh = t >> 6, d = t & 63;
    float run = 0.0f;
    #pragma unroll 8
    for (int ch = 0; ch < NCH; ch++) {
        int ix = (bh*NCH + ch)*DD + d;
        float v = g_csum[ix];
        g_coff[ix] = run;
        run += v;
    }
}

// ---------------- Kernel F3: final cumsum + scatter; 256 thr, 4 segs x 8 rows ----------------
__global__ __launch_bounds__(256) void k_final(const float* __restrict__ V, float* __restrict__ out)
{
    int ch = blockIdx.x, bh = blockIdx.y;
    int b = bh >> 3, h = bh & 7;
    int d = threadIdx.x & 63, seg = threadIdx.x >> 6;
    __shared__ float segsum[4][DD];
    int l0 = ch*CH + seg*8;

    float v[8];
    float tot = 0.0f;
    #pragma unroll
    for (int i = 0; i < 8; i++) { v[i] = V[xoff(b, l0 + i, h, d)]; tot += v[i]; }
    segsum[seg][d] = tot;
    __syncthreads();

    float acc = g_coff[(bh*NCH + ch)*DD + d];
    #pragma unroll
    for (int ss = 0; ss < 3; ss++) if (ss < seg) acc += segsum[ss][d];

    #pragma unroll
    for (int i = 0; i < 8; i++) {
        int l = l0 + i;
        acc += v[i];
        int s = __ldg(&g_sel[bh*LQ + l]);
        int o = xoff(b, l, h, d);
        if (s >= 0) {
            float inv = 1.0f / __ldg(&g_rowsum[bh*UPAD + s]);
            out[o] = g_update[(bh*UPAD + s)*DD + d] * inv;
        } else {
            out[o] = acc;
        }
    }
}

// ---------------- launch ----------------
// R13 launch order (the measured-best ordering), slot 4 = sampleM.
extern "C" void kernel_launch(void* const* d_in, const int* in_sizes, int n_in,
                              void* d_out, int out_size)
{
    const float* Q   = (const float*)d_in[0];
    const float* K   = (const float*)d_in[1];
    const float* V   = (const float*)d_in[2];
    const int*   idx = (const int*)  d_in[3];
    float* out = (float*)d_out;
    int U = in_sizes[3] / LQ;     // 45
    int ncand = (2*U + 6 <= NC) ? 2*U + 6 : NC;   // 96 for U=45
    const int NF4 = NB*LQ*NH*DD/4;                 // total float4 elems in K

    k_csum1    <<<dim3(NCH, BH), 256>>>(V);                  // 1
    k_cvtK     <<<NF4/256, 256>>>(K);                        // 2
    k_csum2    <<<1, 1024>>>();                              // 3
    k_sampleM_bf<<<NB*LQ/8, 256>>>(Q, idx, U);               // 4  <- profiled
    k_cand     <<<BH, 256>>>(ncand);                         // 5
    k_refine   <<<(2*BH*ncand + 7)/8, 256>>>(Q, K, idx, U, ncand); // 6
    k_sel45    <<<BH, 32>>>(U, ncand);                       // 7
    k_fused    <<<dim3(LQ/KC, BH), 256>>>(Q, K, V, U);       // 8
    k_final    <<<dim3(NCH, BH), 256>>>(V, out);             // 9
}